// round 4
// baseline (speedup 1.0000x reference)
#include <cuda_runtime.h>

// ---------------------------------------------------------------------------
// TemporalFootAndBall detection post-process, GB300 (sm_103a)  -- R4
//
// player map: B=64, C=2, H=68,  W=120, ds=16, with bbox regression
// ball map:   B=64, C=2, H=272, W=480, ds=4,  fixed 20x20 boxes
// out: (64, 200, 5) f32
//
// conf = softmax(x)[1] depends only on d = x1 - x0 (bit-exactly: -|d| equals
// min-max after rounding). NMS runs on the cheap d map; the exact XLA-matching
// conf (poly expf + IEEE div) is evaluated lazily: only for local maxima and
// for provable near-ties where conf bits could collapse.
//
// R4 fix vs R3: block-uniform trip count around __ballot_sync/__match_any_sync
// in the select histogram loop (R3 deadlocked: exited lanes named in mask).
// ---------------------------------------------------------------------------

#define B_DIM   64
#define P_H     68
#define P_W     120
#define P_HW    (P_H * P_W)
#define B_H     272
#define B_W     480
#define B_HW    (B_H * B_W)
#define MAXDET  100

#define TXD     32
#define TYD     16
#define BALL_TX (B_W / TXD)            // 15
#define BALL_TY (B_H / TYD)            // 17
#define BALL_TILES (BALL_TX * BALL_TY) // 255
#define PLAY_TX ((P_W + TXD - 1) / TXD) // 4
#define PLAY_TY ((P_H + TYD - 1) / TYD) // 5
#define PLAY_TILES (PLAY_TX * PLAY_TY)  // 20
#define ALL_TILES (BALL_TILES + PLAY_TILES)

// Static scratch (allocation-free). Capacity = hw per row (local maxima count
// can never exceed hw).
__device__ unsigned long long g_cand_p[B_DIM * P_HW];
__device__ unsigned long long g_cand_b[(size_t)B_DIM * B_HW];
__device__ int g_cnt[2 * B_DIM];   // [0,64): player rows, [64,128): ball rows

__global__ void zero_cnt_kernel() {
    g_cnt[threadIdx.x] = 0;
}

// Bit-exact replication of libdevice __nv_expf (what XLA's f32 exp lowers to)
// for arguments in (-88, 0]. fma/exact-scale only -> fast-math-proof.
__device__ __forceinline__ float xla_expf(float a) {
    float j = fmaf(a, 0x1.715476p+0f, 0x1.8p+23f) - 0x1.8p+23f;  // rint(a*log2e)
    float f = fmaf(j, -0x1.62e400p-1f, a);
    f = fmaf(j, -0x1.7f7d1cp-20f, f);
    const int i = (int)j;
    float r = 0x1.694000p-10f;
    r = fmaf(r, f, 0x1.125edcp-7f);
    r = fmaf(r, f, 0x1.555b5ap-5f);
    r = fmaf(r, f, 0x1.555450p-3f);
    r = fmaf(r, f, 0x1.fffff6p-2f);
    r = fmaf(r, f, 1.0f);
    r = fmaf(r, f, 1.0f);
    return r * __uint_as_float((unsigned)(127 + i) << 23);
}

// softmax([x0,x1])[1] as a function of d = x1-x0, bit-identical to
// m=max(x0,x1); e=exp(min-m); conf = e1/(1+e) with IEEE ops.
__device__ __forceinline__ float conf_from_d(float d) {
    const float e = xla_expf(0.0f - fabsf(d));
    const float e1 = (d >= 0.0f) ? 1.0f : e;
    return __fdiv_rn(e1, 1.0f + e);
}

// ---------------------------------------------------------------------------
// Fused NMS over both maps. One tile = 32x16 + 1-px halo of d = x1-x0.
// Keep pixel iff conf(d_c) == conf(dmax9); by monotonicity that is
// (d_c >= dmax8) OR (near-tie AND conf bits collapse).
// ---------------------------------------------------------------------------
template <int H, int W, bool IS_PLAYER>
__device__ __forceinline__ void nms_tile(const float* __restrict__ fm,
                                         int b, int tx, int ty,
                                         float* tile, int* s_cnt, int* s_base) {
    const int tid = threadIdx.y * TXD + threadIdx.x;
    if (tid == 0) *s_cnt = 0;

    const float* f0 = fm + (size_t)b * 2 * H * W;
    const float* f1 = f0 + H * W;
    const int x0 = tx * TXD, y0 = ty * TYD;

    // Load halo tile of d (OOR -> -inf).
    #pragma unroll
    for (int i = tid; i < (TYD + 2) * (TXD + 2); i += TXD * TYD) {
        const int ly = i / (TXD + 2), lx = i % (TXD + 2);
        const int gy = y0 + ly - 1, gx = x0 + lx - 1;
        float d = __int_as_float(0xFF800000);
        if (gy >= 0 && gy < H && gx >= 0 && gx < W) {
            const int o = gy * W + gx;
            d = f1[o] - f0[o];
        }
        tile[i] = d;
    }
    __syncthreads();

    const int gx = x0 + threadIdx.x;
    const int gy = y0 + threadIdx.y;
    bool kept = false;
    unsigned key = 0;
    if (gx < W && gy < H) {
        const float* r0 = tile + threadIdx.y * (TXD + 2) + threadIdx.x;
        const float* r1 = r0 + (TXD + 2);
        const float* r2 = r1 + (TXD + 2);
        const float c = r1[1];
        float dmax = fmaxf(fmaxf(r0[0], r0[1]), r0[2]);
        dmax = fmaxf(dmax, fmaxf(r1[0], r1[2]));
        dmax = fmaxf(dmax, fmaxf(fmaxf(r2[0], r2[1]), r2[2]));
        if (c >= dmax) {
            kept = true;
            key = __float_as_uint(conf_from_d(c));
        } else {
            // conf bits can collapse only if (dmax-c) <= 2^-18 * e^{dm}.
            // Cheap ALU guard on the float exponent of (dmax-c), 1-bit slack
            // each side: take exact path iff E < dm*log2e - 15.
            const float dd = dmax - c;
            const float dm = fmaxf(fabsf(c), fabsf(dmax));
            const int E = (int)((__float_as_uint(dd) >> 23) & 255u) - 127;
            if ((float)E < fmaf(dm, 1.442695041f, -15.0f)) {
                const float cc = conf_from_d(c);
                if (cc == conf_from_d(dmax)) {
                    kept = true;
                    key = __float_as_uint(cc);
                }
            }
        }
    }

    // Warp-aggregated append into per-row candidate list (no divergent loop:
    // every thread of every warp reaches this point exactly once).
    const unsigned bal = __ballot_sync(0xFFFFFFFFu, kept);
    const int lane = tid & 31;
    int my = 0;
    if (bal) {
        const int leader = __ffs(bal) - 1;
        int base = 0;
        if (lane == leader) base = atomicAdd(s_cnt, __popc(bal));
        base = __shfl_sync(0xFFFFFFFFu, base, leader);
        my = base + __popc(bal & ((1u << lane) - 1u));
    }
    __syncthreads();
    if (tid == 0)
        *s_base = atomicAdd(&g_cnt[(IS_PLAYER ? 0 : B_DIM) + b], *s_cnt);
    __syncthreads();
    if (kept) {
        unsigned long long* cand =
            (IS_PLAYER ? g_cand_p : g_cand_b) + (size_t)b * (H * W);
        cand[*s_base + my] =
            ((unsigned long long)key << 32) | (unsigned)(gy * W + gx);
    }
}

__global__ __launch_bounds__(TXD * TYD) void nms_kernel(
    const float* __restrict__ pfm, const float* __restrict__ bfm) {
    __shared__ float tile[(TYD + 2) * (TXD + 2)];
    __shared__ int s_cnt, s_base;
    const int b = blockIdx.z;
    const int t = blockIdx.x;
    if (t < BALL_TILES)
        nms_tile<B_H, B_W, false>(bfm, b, t % BALL_TX, t / BALL_TX,
                                  tile, &s_cnt, &s_base);
    else
        nms_tile<P_H, P_W, true>(pfm, b, (t - BALL_TILES) % PLAY_TX,
                                 (t - BALL_TILES) / PLAY_TX,
                                 tile, &s_cnt, &s_base);
}

// ---------------------------------------------------------------------------
// Per-row top-100: radix descent (warp-aggregated hist) until set <= 512,
// collect, then rank-based direct emission (no sort, no bitonic barriers).
// ---------------------------------------------------------------------------
__global__ __launch_bounds__(1024) void select_kernel(
    const float* __restrict__ pbb, float* __restrict__ out) {
    constexpr int CAP = 2048;
    __shared__ unsigned hist[256];
    __shared__ unsigned long long buf[CAP];
    __shared__ unsigned sh_above, sh_prefix, sh_set, sh_cnt;

    const int blk = blockIdx.x;
    const bool is_player = (blk < B_DIM);
    const int b = is_player ? blk : blk - B_DIM;
    const int n = g_cnt[blk];
    const unsigned long long* cand =
        is_player ? (g_cand_p + (size_t)b * P_HW)
                  : (g_cand_b + (size_t)b * B_HW);
    const int tid = threadIdx.x;
    const int lane = tid & 31;
    const int NT = 1024;                       // blockDim.x (uniform)
    const int nit = (n + NT - 1) / NT;         // block-uniform trip count

    // Radix descent: threshold T with >= MAXDET elements >= T, set small.
    unsigned prefix = 0, above = 0, thresh = 0;
    for (int s = 24;; s -= 8) {
        for (int i = tid; i < 256; i += NT) hist[i] = 0;
        __syncthreads();
        const unsigned mask = (s == 24) ? 0u : (0xFFFFFFFFu << (s + 8));
        // Uniform trip count: every lane executes every iteration, so the
        // warp collectives below are always warp-converged.
        for (int it = 0; it < nit; ++it) {
            const int i = it * NT + tid;
            bool on = false;
            unsigned bin = 0;
            if (i < n) {
                const unsigned sc = (unsigned)(cand[i] >> 32);
                on = ((sc & mask) == prefix);
                bin = (sc >> s) & 255u;
            }
            const unsigned act = __ballot_sync(0xFFFFFFFFu, on);
            if (on) {
                const unsigned grp = __match_any_sync(act, bin);
                if ((__ffs(grp) - 1) == lane)
                    atomicAdd(&hist[bin], (unsigned)__popc(grp));
            }
        }
        __syncthreads();
        if (tid == 0) {
            unsigned acc = above, setc = 0;
            int bin = 0;
            for (int bb = 255; bb >= 0; --bb) {
                if (acc + hist[bb] >= (unsigned)MAXDET || bb == 0) {
                    bin = bb;
                    setc = acc + hist[bb];
                    break;
                }
                acc += hist[bb];
            }
            sh_above  = acc;
            sh_prefix = prefix | ((unsigned)bin << s);
            sh_set    = setc;
        }
        __syncthreads();
        above  = sh_above;
        prefix = sh_prefix;
        if (sh_set <= 512u || s == 0) {
            thresh = prefix;
            break;
        }
    }

    // Collect candidates with score >= thresh; key = (score<<32) | ~idx so
    // larger key == (higher conf, lower idx) == lax.top_k order.
    // (Plain atomics only here: divergent loop is fine.)
    if (tid == 0) sh_cnt = 0;
    __syncthreads();
    for (int i = tid; i < n; i += NT) {
        const unsigned long long cv = cand[i];
        if ((unsigned)(cv >> 32) >= thresh) {
            const unsigned pos = atomicAdd(&sh_cnt, 1u);
            if (pos < (unsigned)CAP)
                buf[pos] = (cv & 0xFFFFFFFF00000000ull) |
                           (unsigned)(~(unsigned)cv);
        }
    }
    __syncthreads();
    const int m = (int)min(sh_cnt, (unsigned)CAP);

    // Rank-based emission: rank_i = #{j : key_j > key_i}; write row rank_i.
    // Keys are distinct (idx unique per row), so ranks are a permutation.
    float* const orow = out + (size_t)b * (2 * MAXDET * 5) +
                        (is_player ? 0 : MAXDET * 5);
    for (int i = tid; i < m; i += NT) {
        const unsigned long long k = buf[i];
        int rank = 0;
        for (int j = 0; j < m; ++j) rank += (buf[j] > k);
        if (rank < MAXDET) {
            const unsigned idx = ~(unsigned)k;
            const float conf = __uint_as_float((unsigned)(k >> 32));
            float o0, o1, o2, o3;
            if (is_player) {
                const int x = (int)idx % P_W;
                const int y = (int)idx / P_W;
                const float xc = (float)x * 16.0f + 7.5f;
                const float yc = (float)y * 16.0f + 7.5f;
                const float* bp = pbb + (size_t)b * 4 * P_HW + idx;
                const float t0 = bp[0 * P_HW] * 1920.0f;
                const float t1 = bp[1 * P_HW] * 1088.0f;
                const float t2 = bp[2 * P_HW] * 1920.0f;
                const float t3 = bp[3 * P_HW] * 1088.0f;
                const float bx = xc + t0, by = yc + t1;
                o0 = bx - 0.5f * t2;
                o1 = by - 0.5f * t3;
                o2 = bx + 0.5f * t2;
                o3 = by + 0.5f * t3;
            } else {
                const int x = (int)idx % B_W;
                const int y = (int)idx / B_W;
                const float xc = (float)x * 4.0f + 1.5f;
                const float yc = (float)y * 4.0f + 1.5f;
                o0 = xc - 10.0f;
                o1 = yc - 10.0f;
                o2 = xc + 10.0f;
                o3 = yc + 10.0f;
            }
            float* op = orow + rank * 5;
            op[0] = o0; op[1] = o1; op[2] = o2; op[3] = o3; op[4] = conf;
        }
    }
    // Pathological (<100 candidates): zero-fill remaining rows.
    if (m < MAXDET) {
        for (int r = m + tid; r < MAXDET; r += NT) {
            float* op = orow + r * 5;
            op[0] = op[1] = op[2] = op[3] = op[4] = 0.0f;
        }
    }
}

// ---------------------------------------------------------------------------

extern "C" void kernel_launch(void* const* d_in, const int* in_sizes, int n_in,
                              void* d_out, int out_size) {
    const float* pfm = nullptr;
    const float* pbb = nullptr;
    const float* bfm = nullptr;
    for (int i = 0; i < n_in; ++i) {
        if (in_sizes[i] == B_DIM * 2 * P_HW)      pfm = (const float*)d_in[i];
        else if (in_sizes[i] == B_DIM * 4 * P_HW) pbb = (const float*)d_in[i];
        else if (in_sizes[i] == B_DIM * 2 * B_HW) bfm = (const float*)d_in[i];
    }
    float* out = (float*)d_out;

    zero_cnt_kernel<<<1, 128>>>();
    nms_kernel<<<dim3(ALL_TILES, 1, B_DIM), dim3(TXD, TYD)>>>(pfm, bfm);
    select_kernel<<<2 * B_DIM, 1024>>>(pbb, out);
}

// round 5
// speedup vs baseline: 1.5269x; 1.5269x over previous
#include <cuda_runtime.h>

// ---------------------------------------------------------------------------
// TemporalFootAndBall detection post-process, GB300 (sm_103a)  -- R5
//
// player map: B=64, C=2, H=68,  W=120, ds=16, with bbox regression
// ball map:   B=64, C=2, H=272, W=480, ds=4,  fixed 20x20 boxes
// out: (64, 200, 5) f32
//
// R5: register-rolling 3x3 NMS (each warp = 30-col strip, 3 rows of d in
// regs, lane+-1 halo via shfl), chunked candidate segments with per-chunk
// plain-store counts (no zero kernel, no global atomics), 2 launches total.
// Exact conf (poly expf + IEEE div, bit-matching XLA) evaluated only for
// keepers and provable near-ties.
// ---------------------------------------------------------------------------

#define B_DIM   64
#define P_H     68
#define P_W     120
#define P_HW    (P_H * P_W)
#define B_H     272
#define B_W     480
#define B_HW    (B_H * B_W)
#define MAXDET  100

#define CHUNKS_B   8                 // ball row-chunks per batch
#define CROWS_B    (B_H / CHUNKS_B)  // 34
#define CAP_B      (CROWS_B * B_W)   // 16320 (cap = pixels in chunk: safe)
#define BALL_CTAS  (B_DIM * CHUNKS_B)  // 512
#define ALL_CTAS   (BALL_CTAS + B_DIM) // + 64 player CTAs

// Static scratch (allocation-free).
__device__ unsigned long long g_cand_b[(size_t)BALL_CTAS * CAP_B];
__device__ unsigned long long g_cand_p[B_DIM * P_HW];
__device__ int g_cnt_b[BALL_CTAS];   // plain stores, rewritten every launch
__device__ int g_cnt_p[B_DIM];

// Bit-exact replication of libdevice __nv_expf (XLA's f32 exp) for args in
// (-88, 0]. fma/exact-scale only -> fast-math-proof.
__device__ __forceinline__ float xla_expf(float a) {
    float j = fmaf(a, 0x1.715476p+0f, 0x1.8p+23f) - 0x1.8p+23f;  // rint
    float f = fmaf(j, -0x1.62e400p-1f, a);
    f = fmaf(j, -0x1.7f7d1cp-20f, f);
    const int i = (int)j;
    float r = 0x1.694000p-10f;
    r = fmaf(r, f, 0x1.125edcp-7f);
    r = fmaf(r, f, 0x1.555b5ap-5f);
    r = fmaf(r, f, 0x1.555450p-3f);
    r = fmaf(r, f, 0x1.fffff6p-2f);
    r = fmaf(r, f, 1.0f);
    r = fmaf(r, f, 1.0f);
    return r * __uint_as_float((unsigned)(127 + i) << 23);
}

// softmax([x0,x1])[1] as a function of d = x1-x0, bit-identical to
// m=max; e=exp(min-m); conf=e1/(1+e) with IEEE ops.
__device__ __forceinline__ float conf_from_d(float d) {
    const float e = xla_expf(0.0f - fabsf(d));
    const float e1 = (d >= 0.0f) ? 1.0f : e;
    return __fdiv_rn(e1, 1.0f + e);
}

__device__ __forceinline__ float load_d(const float* __restrict__ f0,
                                        const float* __restrict__ f1,
                                        int H, int W, int gx, int y,
                                        bool inx) {
    if (!inx || y < 0 || y >= H) return __int_as_float(0xFF800000);
    const int o = y * W + gx;
    return f1[o] - f0[o];
}

// ---------------------------------------------------------------------------
// NMS: grid.x in [0, 512): ball chunk CTAs; [512, 576): player CTAs.
// Block = 512 threads = 16 warps; each warp owns a 30-output-column strip
// (lanes 0 / 31 are halo) and rolls down its row range.
// ---------------------------------------------------------------------------
__global__ __launch_bounds__(512) void nms_kernel(
    const float* __restrict__ pfm, const float* __restrict__ bfm) {
    __shared__ int s_cnt;
    const int tid = threadIdx.x, wid = tid >> 5, lane = tid & 31;
    if (tid == 0) s_cnt = 0;
    __syncthreads();

    const bool is_play = (blockIdx.x >= BALL_CTAS);
    int H, W, gx, y0, nrows;
    const float* f0;
    unsigned long long* seg;
    if (!is_play) {
        const int b = blockIdx.x >> 3, chunk = blockIdx.x & 7;
        H = B_H; W = B_W;
        gx = wid * 30 + lane - 1;                 // 16 warp-cols x 30 = 480
        y0 = chunk * CROWS_B; nrows = CROWS_B;
        f0 = bfm + (size_t)b * 2 * B_HW;
        seg = g_cand_b + (size_t)blockIdx.x * CAP_B;
    } else {
        const int b = blockIdx.x - BALL_CTAS;
        H = P_H; W = P_W;
        const int wcol = wid & 3, rc = wid >> 2;  // 4 cols x 4 row-chunks
        gx = wcol * 30 + lane - 1;                // 4 x 30 = 120
        y0 = rc * 17; nrows = 17;                 // 4 x 17 = 68
        f0 = pfm + (size_t)b * 2 * P_HW;
        seg = g_cand_p + (size_t)b * P_HW;
    }
    const float* f1 = f0 + H * W;
    const bool inx = (gx >= 0 && gx < W);
    const bool owner = inx && lane >= 1 && lane <= 30;

    float dm1 = load_d(f0, f1, H, W, gx, y0 - 1, inx);
    float d0  = load_d(f0, f1, H, W, gx, y0,     inx);

    for (int r = 0; r < nrows; ++r) {            // warp-uniform trip count
        const int y = y0 + r;
        const float dp1 = load_d(f0, f1, H, W, gx, y + 1, inx);
        const float vm = fmaxf(fmaxf(dm1, d0), dp1);
        const float vl = __shfl_up_sync(0xFFFFFFFFu, vm, 1);
        const float vr = __shfl_down_sync(0xFFFFFFFFu, vm, 1);
        const float p  = fmaxf(vm, fmaxf(vl, vr));  // pooled 3x3 max (incl c)

        bool kept = false;
        unsigned key = 0;
        if (owner) {
            const float c = d0;
            if (c == p) {                        // x == pooled in d-space
                kept = true;
                key = __float_as_uint(conf_from_d(c));
            } else {
                // conf bits can collapse only if (p-c) <= 2^-18 * e^{dm}.
                // Exponent-space guard (1-bit slack each side).
                const float dd = p - c;
                const float dm = fmaxf(fabsf(c), fabsf(p));
                const int E =
                    (int)((__float_as_uint(dd) >> 23) & 255u) - 127;
                if ((float)E < fmaf(dm, 1.442695041f, -15.0f)) {
                    const float cc = conf_from_d(c);
                    if (cc == conf_from_d(p)) {
                        kept = true;
                        key = __float_as_uint(cc);
                    }
                }
            }
        }
        const unsigned bal = __ballot_sync(0xFFFFFFFFu, kept);
        if (bal) {
            const int leader = __ffs(bal) - 1;
            int base = 0;
            if (lane == leader) base = atomicAdd(&s_cnt, __popc(bal));
            base = __shfl_sync(0xFFFFFFFFu, base, leader);
            if (kept)
                seg[base + __popc(bal & ((1u << lane) - 1u))] =
                    ((unsigned long long)key << 32) | (unsigned)(y * W + gx);
        }
        dm1 = d0;
        d0 = dp1;
    }
    __syncthreads();
    if (tid == 0) {
        if (is_play) g_cnt_p[blockIdx.x - BALL_CTAS] = s_cnt;
        else         g_cnt_b[blockIdx.x] = s_cnt;
    }
}

// ---------------------------------------------------------------------------
// Per-row top-100: radix descent (plain smem atomics) until set <= 256,
// collect, rank-based direct emission. blk<64: player; else ball.
// ---------------------------------------------------------------------------
__global__ __launch_bounds__(1024) void select_kernel(
    const float* __restrict__ pbb, float* __restrict__ out) {
    constexpr int CAP = 1024;
    __shared__ unsigned hist[256];
    __shared__ unsigned long long buf[CAP];
    __shared__ unsigned sh_above, sh_prefix, sh_set, sh_cnt;

    const int blk = blockIdx.x;
    const bool is_player = (blk < B_DIM);
    const int b = is_player ? blk : blk - B_DIM;
    const int tid = threadIdx.x;
    const int NT = 1024;

    const int nseg = is_player ? 1 : CHUNKS_B;

    // Radix descent.
    unsigned prefix = 0, above = 0, thresh = 0;
    for (int s = 24;; s -= 8) {
        for (int i = tid; i < 256; i += NT) hist[i] = 0;
        __syncthreads();
        const unsigned mask = (s == 24) ? 0u : (0xFFFFFFFFu << (s + 8));
        for (int sg = 0; sg < nseg; ++sg) {
            const unsigned long long* cand;
            int cnt;
            if (is_player) {
                cand = g_cand_p + (size_t)b * P_HW;
                cnt = g_cnt_p[b];
            } else {
                cand = g_cand_b + (size_t)(b * CHUNKS_B + sg) * CAP_B;
                cnt = g_cnt_b[b * CHUNKS_B + sg];
            }
            for (int i = tid; i < cnt; i += NT) {
                const unsigned sc = (unsigned)(cand[i] >> 32);
                if ((sc & mask) == prefix)
                    atomicAdd(&hist[(sc >> s) & 255u], 1u);
            }
        }
        __syncthreads();
        if (tid == 0) {
            unsigned acc = above, setc = 0;
            int bin = 0;
            for (int bb = 255; bb >= 0; --bb) {
                if (acc + hist[bb] >= (unsigned)MAXDET || bb == 0) {
                    bin = bb;
                    setc = acc + hist[bb];
                    break;
                }
                acc += hist[bb];
            }
            sh_above  = acc;
            sh_prefix = prefix | ((unsigned)bin << s);
            sh_set    = setc;
        }
        __syncthreads();
        above  = sh_above;
        prefix = sh_prefix;
        if (sh_set <= 256u || s == 0) {
            thresh = prefix;
            break;
        }
    }

    // Collect candidates >= thresh; key = (conf_bits<<32) | ~idx so larger
    // key == (higher conf, lower idx) == lax.top_k order.
    if (tid == 0) sh_cnt = 0;
    __syncthreads();
    for (int sg = 0; sg < nseg; ++sg) {
        const unsigned long long* cand;
        int cnt;
        if (is_player) {
            cand = g_cand_p + (size_t)b * P_HW;
            cnt = g_cnt_p[b];
        } else {
            cand = g_cand_b + (size_t)(b * CHUNKS_B + sg) * CAP_B;
            cnt = g_cnt_b[b * CHUNKS_B + sg];
        }
        for (int i = tid; i < cnt; i += NT) {
            const unsigned long long cv = cand[i];
            if ((unsigned)(cv >> 32) >= thresh) {
                const unsigned pos = atomicAdd(&sh_cnt, 1u);
                if (pos < (unsigned)CAP)
                    buf[pos] = (cv & 0xFFFFFFFF00000000ull) |
                               (unsigned)(~(unsigned)cv);
            }
        }
    }
    __syncthreads();
    const int m = (int)min(sh_cnt, (unsigned)CAP);

    // Rank-based emission (keys distinct -> ranks are a permutation).
    float* const orow = out + (size_t)b * (2 * MAXDET * 5) +
                        (is_player ? 0 : MAXDET * 5);
    for (int i = tid; i < m; i += NT) {
        const unsigned long long k = buf[i];
        int rank = 0;
        for (int j = 0; j < m; ++j) rank += (buf[j] > k);
        if (rank < MAXDET) {
            const unsigned idx = ~(unsigned)k;
            const float conf = __uint_as_float((unsigned)(k >> 32));
            float o0, o1, o2, o3;
            if (is_player) {
                const int x = (int)idx % P_W;
                const int y = (int)idx / P_W;
                const float xc = (float)x * 16.0f + 7.5f;
                const float yc = (float)y * 16.0f + 7.5f;
                const float* bp = pbb + (size_t)b * 4 * P_HW + idx;
                const float t0 = bp[0 * P_HW] * 1920.0f;
                const float t1 = bp[1 * P_HW] * 1088.0f;
                const float t2 = bp[2 * P_HW] * 1920.0f;
                const float t3 = bp[3 * P_HW] * 1088.0f;
                const float bx = xc + t0, by = yc + t1;
                o0 = bx - 0.5f * t2;
                o1 = by - 0.5f * t3;
                o2 = bx + 0.5f * t2;
                o3 = by + 0.5f * t3;
            } else {
                const int x = (int)idx % B_W;
                const int y = (int)idx / B_W;
                const float xc = (float)x * 4.0f + 1.5f;
                const float yc = (float)y * 4.0f + 1.5f;
                o0 = xc - 10.0f;
                o1 = yc - 10.0f;
                o2 = xc + 10.0f;
                o3 = yc + 10.0f;
            }
            float* op = orow + rank * 5;
            op[0] = o0; op[1] = o1; op[2] = o2; op[3] = o3; op[4] = conf;
        }
    }
    if (m < MAXDET) {  // pathological; never hit with this data
        for (int r = m + tid; r < MAXDET; r += NT) {
            float* op = orow + r * 5;
            op[0] = op[1] = op[2] = op[3] = op[4] = 0.0f;
        }
    }
}

// ---------------------------------------------------------------------------

extern "C" void kernel_launch(void* const* d_in, const int* in_sizes, int n_in,
                              void* d_out, int out_size) {
    const float* pfm = nullptr;
    const float* pbb = nullptr;
    const float* bfm = nullptr;
    for (int i = 0; i < n_in; ++i) {
        if (in_sizes[i] == B_DIM * 2 * P_HW)      pfm = (const float*)d_in[i];
        else if (in_sizes[i] == B_DIM * 4 * P_HW) pbb = (const float*)d_in[i];
        else if (in_sizes[i] == B_DIM * 2 * B_HW) bfm = (const float*)d_in[i];
    }
    float* out = (float*)d_out;

    nms_kernel<<<ALL_CTAS, 512>>>(pfm, bfm);
    select_kernel<<<2 * B_DIM, 1024>>>(pbb, out);
}